// round 6
// baseline (speedup 1.0000x reference)
#include <cuda_runtime.h>
#include <cstdint>

// MeanCellExtrator v5: warp-specialized producer/consumer, conflict-free RMW.
//   - grid (74,4) = 296 CTAs, 512 thr, 2 CTAs/SM (102.6 KB smem).
//   - producers (warps 4-15): cp.async 128-px channel rows -> double-buffered
//     smem stage (row stride 132 => consumer LDS bank-conflict-free).
//   - consumers (warps 0-3, one per SMSP): warp w owns channels [8w,8w+8).
//     32 lanes = 8 ch x 4 px per iter; acc[ch*513+L] bank = (ch+L)%32 =>
//     conflict-free, race-free, NO match/fold. Dup labels among the 4 px
//     (P~1.2%) detected via 3 shfl + ballot, serialized fallback.
//   - label 0 (background) accumulates into unread slot 0: no predication.
//   - merge via red.global.add.v4 into __device__ scratch; last CTA finalizes
//     into d_out and re-zeros scratch (deterministic graph replays).

#define FULLMASK 0xffffffffu

constexpr int C       = 16;
constexpr int HW      = 1 << 20;
constexpr int NLAB    = 512;
constexpr int TILE    = 128;
constexpr int NT_IMG  = HW / TILE;        // 8192 tiles per image
constexpr int SCTA    = 74;               // CTAs per image (296 total = 2/SM)
constexpr int RSTR    = 513;              // acc row stride: bank = (ch+L)%32
constexpr int ACC_PAD = 16932;            // 32*513 acc + 513 cnt, padded 16B
constexpr int SROW    = 132;              // stage row stride: bank=(4ch+px)%32
constexpr int SBUF    = 33 * SROW;        // 32 value rows + 1 label row = 4356
constexpr int SMEM_F  = ACC_PAD + 2 * SBUF;   // 25644 floats = 102576 B

__device__ __align__(16) float g_acc[67584];
__device__ unsigned g_done = 0;

__device__ __forceinline__ void red4(float* p, float a, float b, float c, float d) {
    asm volatile("red.global.add.v4.f32 [%0], {%1,%2,%3,%4};"
                 :: "l"(p), "f"(a), "f"(b), "f"(c), "f"(d) : "memory");
}
__device__ __forceinline__ void cpasync16(uint32_t dst, const void* src) {
    asm volatile("cp.async.cg.shared.global [%0], [%1], 16;"
                 :: "r"(dst), "l"(src) : "memory");
}

__global__ __launch_bounds__(512, 2)
void fused_kernel(const float* __restrict__ pred,
                  const float* __restrict__ targ,
                  const int*   __restrict__ nuc,
                  float* __restrict__ out, int nCTA)
{
    extern __shared__ float sm[];
    float* acc = sm;                   // [32][513]
    float* cnt = sm + 32 * RSTR;       // [513]
    __shared__ int lastFlag;

    const int tid  = threadIdx.x;
    const int wid  = tid >> 5;
    const int lane = tid & 31;
    const int b    = blockIdx.y;
    const int s    = blockIdx.x;

    uint32_t smBase;
    asm("{ .reg .u64 t; cvta.to.shared.u64 t, %1; cvt.u32.u64 %0, t; }"
        : "=r"(smBase) : "l"(sm));

    // ---- zero accumulators ----
    {
        float4 z = make_float4(0.f, 0.f, 0.f, 0.f);
        float4* p4 = reinterpret_cast<float4*>(sm);
        for (int i = tid; i < (ACC_PAD >> 2); i += 512) p4[i] = z;
    }

    const int  ntiles = (NT_IMG - s + SCTA - 1) / SCTA;
    const bool isProd = (wid >= 4);
    const int  p      = wid - 4;                 // producer index 0..11

    const float* basep = pred + (size_t)b * C * HW;
    const float* baset = targ + (size_t)b * C * HW;
    const int*   lab   = nuc  + (size_t)b * HW;

    auto issueTile = [&](int i, int buf) {
        const int px0 = (s + i * SCTA) * TILE;
        const uint32_t sb = smBase + (uint32_t)(ACC_PAD + buf * SBUF) * 4u;
        #pragma unroll
        for (int k = 0; k < 3; ++k) {
            const int r = p + 12 * k;
            if (r <= 32) {
                const void* src;
                if (r == 32)      src = lab   + px0 + 4 * lane;
                else if (r < 16)  src = basep + (size_t)r * HW + px0 + 4 * lane;
                else              src = baset + (size_t)(r - 16) * HW + px0 + 4 * lane;
                cpasync16(sb + (uint32_t)(r * SROW + 4 * lane) * 4u, src);
            }
        }
        asm volatile("cp.async.commit_group;" ::: "memory");
    };

    // consumer mapping: lane = ch_off*4 + pxq
    const int chOff = lane >> 2;
    const int pxq   = lane & 3;
    const int ch    = wid * 8 + chOff;
    float* accRow = acc + ch * RSTR;
    const bool cntLane = (wid == 0) && (chOff == 0);

    if (isProd && ntiles > 0) issueTile(0, 0);

    for (int i = 0; i < ntiles; ++i) {
        const int buf = i & 1;
        if (isProd) {
            if (i + 1 < ntiles) {
                issueTile(i + 1, buf ^ 1);
                asm volatile("cp.async.wait_group 1;" ::: "memory");
            } else {
                asm volatile("cp.async.wait_group 0;" ::: "memory");
            }
        }
        __syncthreads();                      // stage[buf] ready for all

        if (!isProd) {
            const float* sv = sm + ACC_PAD + buf * SBUF;
            const int*   sl = (const int*)(sv + 32 * SROW);
            const float* vrow = sv + ch * SROW;
            #pragma unroll 4
            for (int j = 0; j < 32; ++j) {
                const int px = 4 * j + pxq;
                const int   L = sl[px];
                const float v = vrow[px];
                const int l1 = __shfl_xor_sync(FULLMASK, L, 1);
                const int l2 = __shfl_xor_sync(FULLMASK, L, 2);
                const int l3 = __shfl_xor_sync(FULLMASK, L, 3);
                const bool dupl = (L == l1) | (L == l2) | (L == l3);
                if (__ballot_sync(FULLMASK, dupl) == 0) {
                    accRow[L] += v;                       // conflict-free RMW
                    if (cntLane) cnt[L] += 1.0f;
                } else {                                  // rare (~1.2%)
                    #pragma unroll
                    for (int q = 0; q < 4; ++q) {
                        if (pxq == q) {
                            accRow[L] += v;
                            if (cntLane) cnt[L] += 1.0f;
                        }
                        __syncwarp();
                    }
                }
            }
        }
        __syncthreads();                      // consumption done before reuse
    }

    // ---- merge partials into global scratch ----
    if (tid < NLAB) {
        const int   L = tid + 1;
        const float c = cnt[L];
        if (c != 0.f) {
            const int gi = b * NLAB + tid;
            float* po = g_acc + (size_t)gi * C;
            float* to = g_acc + 32768 + (size_t)gi * C;
            #pragma unroll
            for (int k = 0; k < 16; k += 4)
                red4(po + k, acc[k * RSTR + L],        acc[(k + 1) * RSTR + L],
                             acc[(k + 2) * RSTR + L],  acc[(k + 3) * RSTR + L]);
            #pragma unroll
            for (int k = 0; k < 16; k += 4)
                red4(to + k, acc[(16 + k) * RSTR + L], acc[(17 + k) * RSTR + L],
                             acc[(18 + k) * RSTR + L], acc[(19 + k) * RSTR + L]);
            atomicAdd(g_acc + 65536 + gi, c);
        }
    }
    __threadfence();
    __syncthreads();
    if (tid == 0) lastFlag = (atomicAdd(&g_done, 1u) == (unsigned)(nCTA - 1));
    __syncthreads();

    // ---- last CTA: finalize into d_out, re-zero scratch ----
    if (lastFlag) {
        __threadfence();
        const float4 z = make_float4(0.f, 0.f, 0.f, 0.f);
        for (int i = tid; i < 4 * NLAB; i += 512) {
            const float c = g_acc[65536 + i];
            const float inv = 1.0f / fmaxf(c, 1.0f);
            float4* gp = reinterpret_cast<float4*>(g_acc + (size_t)i * C);
            float4* gt = reinterpret_cast<float4*>(g_acc + 32768 + (size_t)i * C);
            float4* op = reinterpret_cast<float4*>(out + (size_t)i * C);
            float4* ot = reinterpret_cast<float4*>(out + 32768 + (size_t)i * C);
            #pragma unroll
            for (int q = 0; q < 4; ++q) {
                float4 vp = gp[q], vt = gt[q];
                vp.x *= inv; vp.y *= inv; vp.z *= inv; vp.w *= inv;
                vt.x *= inv; vt.y *= inv; vt.z *= inv; vt.w *= inv;
                op[q] = vp; ot[q] = vt;
                gp[q] = z;  gt[q] = z;
            }
            out[65536 + i]   = (c > 0.f) ? (float)((i & (NLAB - 1)) + 1) : 0.f;
            g_acc[65536 + i] = 0.f;
        }
        __syncthreads();
        if (tid == 0) g_done = 0u;
    }
}

extern "C" void kernel_launch(void* const* d_in, const int* in_sizes, int n_in,
                              void* d_out, int out_size)
{
    const float* pred = (const float*)d_in[0];
    const float* targ = (const float*)d_in[1];
    const int*   nuc  = (const int*)d_in[2];
    float* out = (float*)d_out;

    const int B = in_sizes[2] / HW;   // 4

    const int smemB = SMEM_F * (int)sizeof(float);
    cudaFuncSetAttribute(fused_kernel,
                         cudaFuncAttributeMaxDynamicSharedMemorySize, smemB);

    dim3 grid(SCTA, B);
    fused_kernel<<<grid, 512, smemB>>>(pred, targ, nuc, out, SCTA * B);
}

// round 8
// speedup vs baseline: 1.3674x; 1.3674x over previous
#include <cuda_runtime.h>
#include <cstdint>

// MeanCellExtrator v6: v3.1 + doubled LDG MLP (256-px groups).
//   - grid (111,4) = 444 CTAs, 256 thr, 3 CTAs/SM.
//   - warp w owns channel-slots [4w,4w+4) (w<4: pred, w>=4: targ) -> race-free.
//   - group = 256 px: 8 front-batched LDG.128 per warp-iter (MLP 8, was 4),
//     then two independent 4-px match/fold blocks.
//   - labels staged per-CTA into smem; prefetch.global.L2 next group.
//   - scalar smem RMW acc[slot][513]; merge via red.global.add.v4 into
//     __device__ scratch; last CTA finalizes into d_out, re-zeros scratch.

#define FULLMASK 0xffffffffu

constexpr int C       = 16;
constexpr int HW      = 1 << 20;
constexpr int NLAB    = 512;
constexpr int STRIPS  = 111;             // 111*4 = 444 CTAs = 3/SM
constexpr int NG      = HW / 256;        // 4096 groups of 256 px per image
constexpr int RSTR    = 513;             // acc row stride (floats)
constexpr int ACC_F   = 33 * RSTR;       // 16929
constexpr int ACC_PAD = (ACC_F + 3) & ~3;        // 16932, slab 16B-aligned
constexpr int STAGE_G = 4;               // groups per label stage
constexpr int LAB_I   = STAGE_G * 256;   // 1024 staged labels
constexpr int SMEM_F  = ACC_PAD + LAB_I; // 17956 floats = 71824 B

__device__ __align__(16) float g_acc[67584];
__device__ unsigned g_done = 0;

__device__ __forceinline__ void red4(float* p, float a, float b, float c, float d) {
    asm volatile("red.global.add.v4.f32 [%0], {%1,%2,%3,%4};"
                 :: "l"(p), "f"(a), "f"(b), "f"(c), "f"(d) : "memory");
}

__global__ __launch_bounds__(256, 3)
void fused_kernel(const float* __restrict__ pred,
                  const float* __restrict__ targ,
                  const int*   __restrict__ nuc,
                  float* __restrict__ out, int nCTA)
{
    extern __shared__ float sm[];
    float* cnt  = sm + 32 * RSTR;
    int*   slab = (int*)(sm + ACC_PAD);
    __shared__ int lastFlag;

    const int tid  = threadIdx.x;
    const int warp = tid >> 5;
    const int lane = tid & 31;
    const int b    = blockIdx.y;
    const int s    = blockIdx.x;

    // ---- zero accumulators ----
    {
        float4 z = make_float4(0.f, 0.f, 0.f, 0.f);
        float4* p4 = reinterpret_cast<float4*>(sm);
        for (int i = tid; i < (ACC_PAD >> 2); i += 256) p4[i] = z;
    }

    const float* planeBase = ((warp >= 4) ? targ : pred)
                             + (size_t)(b * C + (warp & 3) * 4) * HW;
    const int* lab = nuc + (size_t)b * HW;
    float* a0 = sm + (4 * warp + 0) * RSTR;
    float* a1 = sm + (4 * warp + 1) * RSTR;
    float* a2 = sm + (4 * warp + 2) * RSTR;
    float* a3 = sm + (4 * warp + 3) * RSTR;
    const bool doCnt = (warp == 0);

    const int g0 = (s * NG) / STRIPS;
    const int g1 = ((s + 1) * NG) / STRIPS;

    for (int gs = g0; gs < g1; gs += STAGE_G) {
        const int ge = min(gs + STAGE_G, g1);
        __syncthreads();   // WAR on slab (and first-iter acc-zero ordering)
        {
            const int n4 = ((ge - gs) * 256) >> 2;
            int4* dst = (int4*)slab;
            const int4* src = (const int4*)(lab + gs * 256);
            for (int i = tid; i < n4; i += 256) dst[i] = __ldg(src + i);
        }
        __syncthreads();

        for (int g = gs; g < ge; ++g) {
            const int baseG = (g << 8) + (lane << 2);

            // prefetch next group's planes into L2
            if (g + 1 < NG) {
                const float* nb = planeBase + (size_t)(((g + 1) << 8) + (lane << 2));
                #pragma unroll
                for (int pl = 0; pl < 4; ++pl) {
                    asm volatile("prefetch.global.L2 [%0];"
                                 :: "l"(nb + (size_t)pl * HW));
                    asm volatile("prefetch.global.L2 [%0];"
                                 :: "l"(nb + (size_t)pl * HW + 128));
                }
            }

            // front-batch 8 independent LDG.128 (MLP 8)
            float4 A0 = __ldg((const float4*)(planeBase + baseG));
            float4 A1 = __ldg((const float4*)(planeBase + HW + baseG));
            float4 A2 = __ldg((const float4*)(planeBase + 2 * (size_t)HW + baseG));
            float4 A3 = __ldg((const float4*)(planeBase + 3 * (size_t)HW + baseG));
            float4 B0 = __ldg((const float4*)(planeBase + baseG + 128));
            float4 B1 = __ldg((const float4*)(planeBase + HW + baseG + 128));
            float4 B2 = __ldg((const float4*)(planeBase + 2 * (size_t)HW + baseG + 128));
            float4 B3 = __ldg((const float4*)(planeBase + 3 * (size_t)HW + baseG + 128));
            const int sOff = ((g - gs) << 8) + (lane << 2);
            int4 LA = *(const int4*)(slab + sOff);
            int4 LB = *(const int4*)(slab + sOff + 128);

            #pragma unroll
            for (int h = 0; h < 2; ++h) {
                const int4   L  = h ? LB : LA;
                const float4 V0 = h ? B0 : A0;
                const float4 V1 = h ? B1 : A1;
                const float4 V2 = h ? B2 : A2;
                const float4 V3 = h ? B3 : A3;
                const int   lv[4] = {L.x, L.y, L.z, L.w};
                const float c0[4] = {V0.x, V0.y, V0.z, V0.w};
                const float c1[4] = {V1.x, V1.y, V1.z, V1.w};
                const float c2[4] = {V2.x, V2.y, V2.z, V2.w};
                const float c3[4] = {V3.x, V3.y, V3.z, V3.w};

                #pragma unroll
                for (int j = 0; j < 4; ++j) {
                    const int label = lv[j];
                    float v0 = c0[j], v1 = c1[j], v2 = c2[j], v3 = c3[j];

                    const bool act = ((unsigned)(label - 1)) < (unsigned)NLAB;
                    const unsigned key = act ? (unsigned)label : (0x8000u | lane);
                    const unsigned grp = __match_any_sync(FULLMASK, key);
                    const int  leader   = __ffs(grp) - 1;
                    const bool isLeader = act && (lane == leader);

                    unsigned rem = grp & (grp - 1);
                    while (__ballot_sync(FULLMASK, rem)) {
                        const int src = rem ? (__ffs(rem) - 1) : lane;
                        const float f0 = __shfl_sync(FULLMASK, v0, src);
                        const float f1 = __shfl_sync(FULLMASK, v1, src);
                        const float f2 = __shfl_sync(FULLMASK, v2, src);
                        const float f3 = __shfl_sync(FULLMASK, v3, src);
                        if (isLeader && rem) { v0 += f0; v1 += f1; v2 += f2; v3 += f3; }
                        rem &= rem - 1;
                    }

                    if (isLeader) {
                        a0[label] += v0;
                        a1[label] += v1;
                        a2[label] += v2;
                        a3[label] += v3;
                        if (doCnt) cnt[label] += (float)__popc(grp);
                    }
                }
            }
        }
    }
    __syncthreads();

    // ---- merge partials into global scratch ----
    for (int r = tid; r < NLAB; r += 256) {
        const int   L = r + 1;
        const float c = cnt[L];
        if (c != 0.f) {
            const int gi = b * NLAB + r;
            float* po = g_acc + (size_t)gi * C;
            float* to = g_acc + 32768 + (size_t)gi * C;
            #pragma unroll
            for (int k = 0; k < 16; k += 4)
                red4(po + k, sm[k * RSTR + L], sm[(k + 1) * RSTR + L],
                             sm[(k + 2) * RSTR + L], sm[(k + 3) * RSTR + L]);
            #pragma unroll
            for (int k = 0; k < 16; k += 4)
                red4(to + k, sm[(16 + k) * RSTR + L], sm[(17 + k) * RSTR + L],
                             sm[(18 + k) * RSTR + L], sm[(19 + k) * RSTR + L]);
            atomicAdd(g_acc + 65536 + gi, c);
        }
    }
    __threadfence();
    __syncthreads();
    if (tid == 0) lastFlag = (atomicAdd(&g_done, 1u) == (unsigned)(nCTA - 1));
    __syncthreads();

    // ---- last CTA: finalize into d_out, re-zero scratch ----
    if (lastFlag) {
        __threadfence();
        const float4 z = make_float4(0.f, 0.f, 0.f, 0.f);
        for (int i = tid; i < 4 * NLAB; i += 256) {
            const float c = g_acc[65536 + i];
            const float inv = 1.0f / fmaxf(c, 1.0f);
            float4* gp = reinterpret_cast<float4*>(g_acc + (size_t)i * C);
            float4* gt = reinterpret_cast<float4*>(g_acc + 32768 + (size_t)i * C);
            float4* op = reinterpret_cast<float4*>(out + (size_t)i * C);
            float4* ot = reinterpret_cast<float4*>(out + 32768 + (size_t)i * C);
            #pragma unroll
            for (int q = 0; q < 4; ++q) {
                float4 vp = gp[q], vt = gt[q];
                vp.x *= inv; vp.y *= inv; vp.z *= inv; vp.w *= inv;
                vt.x *= inv; vt.y *= inv; vt.z *= inv; vt.w *= inv;
                op[q] = vp; ot[q] = vt;
                gp[q] = z;  gt[q] = z;
            }
            out[65536 + i]   = (c > 0.f) ? (float)((i & (NLAB - 1)) + 1) : 0.f;
            g_acc[65536 + i] = 0.f;
        }
        __syncthreads();
        if (tid == 0) g_done = 0u;
    }
}

extern "C" void kernel_launch(void* const* d_in, const int* in_sizes, int n_in,
                              void* d_out, int out_size)
{
    const float* pred = (const float*)d_in[0];
    const float* targ = (const float*)d_in[1];
    const int*   nuc  = (const int*)d_in[2];
    float* out = (float*)d_out;

    const int B = in_sizes[2] / HW;   // 4

    const int smemB = SMEM_F * (int)sizeof(float);
    cudaFuncSetAttribute(fused_kernel,
                         cudaFuncAttributeMaxDynamicSharedMemorySize, smemB);

    dim3 grid(STRIPS, B);
    fused_kernel<<<grid, 256, smemB>>>(pred, targ, nuc, out, STRIPS * B);
}

// round 9
// speedup vs baseline: 1.4683x; 1.0738x over previous
#include <cuda_runtime.h>
#include <cstdint>

// MeanCellExtrator v7: v3.1 architecture, fold-free duplicate handling.
//   - grid (111,4) = 444 CTAs, 256 thr, 3 CTAs/SM.
//   - warp w owns channels [4w,4w+4) (w<4: pred, w>=4: targ) -> race-free
//     across warps. Within warp: dup labels serialized via RANK ROUNDS:
//     rank = popc(match & lanemask_lt), mx = __reduce_max_sync(rank);
//     round r lanes RMW -> distinct labels per round, program order across
//     rounds. No shuffles, no ballots, no divergent fold loop.
//   - label 0 accumulates into never-read slot 0 (no predication).
//   - acc packed float2 per channel-pair: 2xLDS.64 RMW per lane-step.
//   - labels staged per-CTA in smem; prefetch.global.L2 next group.
//   - merge via red.global.add.v4 into __device__ scratch; last CTA
//     finalizes into d_out and re-zeros scratch.

#define FULLMASK 0xffffffffu

constexpr int C       = 16;
constexpr int HW      = 1 << 20;
constexpr int NLAB    = 512;
constexpr int STRIPS  = 111;             // 444 CTAs = 3/SM
constexpr int NG      = HW / 128;        // 8192 groups of 128 px per image
constexpr int PROW    = 1026;            // float2 pair-row stride in floats (513*2)
constexpr int ACC_F   = 16 * PROW + 513; // 16 pair rows + cnt = 16929
constexpr int ACC_PAD = (ACC_F + 3) & ~3;        // 16932, slab 16B-aligned
constexpr int STAGE_G = 8;
constexpr int LAB_I   = STAGE_G * 128;   // 1024 staged labels
constexpr int SMEM_F  = ACC_PAD + LAB_I; // 17956 floats = 71824 B

__device__ __align__(16) float g_acc[67584];
__device__ unsigned g_done = 0;

__device__ __forceinline__ void red4(float* p, float a, float b, float c, float d) {
    asm volatile("red.global.add.v4.f32 [%0], {%1,%2,%3,%4};"
                 :: "l"(p), "f"(a), "f"(b), "f"(c), "f"(d) : "memory");
}

__global__ __launch_bounds__(256, 3)
void fused_kernel(const float* __restrict__ pred,
                  const float* __restrict__ targ,
                  const int*   __restrict__ nuc,
                  float* __restrict__ out, int nCTA)
{
    extern __shared__ float sm[];
    float*  cnt  = sm + 16 * PROW;
    int*    slab = (int*)(sm + ACC_PAD);
    __shared__ int lastFlag;

    const int tid  = threadIdx.x;
    const int warp = tid >> 5;
    const int lane = tid & 31;
    const int b    = blockIdx.y;
    const int s    = blockIdx.x;

    // ---- zero accumulators ----
    {
        float4 z = make_float4(0.f, 0.f, 0.f, 0.f);
        float4* p4 = reinterpret_cast<float4*>(sm);
        for (int i = tid; i < (ACC_PAD >> 2); i += 256) p4[i] = z;
    }

    const float* planeBase = ((warp >= 4) ? targ : pred)
                             + (size_t)(b * C + (warp & 3) * 4) * HW;
    const int* lab = nuc + (size_t)b * HW;
    float2* pairA = reinterpret_cast<float2*>(sm + (2 * warp)     * PROW);
    float2* pairB = reinterpret_cast<float2*>(sm + (2 * warp + 1) * PROW);
    const bool doCnt = (warp == 0);

    const int g0 = (s * NG) / STRIPS;
    const int g1 = ((s + 1) * NG) / STRIPS;

    for (int gs = g0; gs < g1; gs += STAGE_G) {
        const int ge = min(gs + STAGE_G, g1);
        __syncthreads();   // WAR on slab (and first-iter acc-zero ordering)
        {
            const int n4 = ((ge - gs) * 128) >> 2;
            int4* dst = (int4*)slab;
            const int4* src = (const int4*)(lab + gs * 128);
            for (int i = tid; i < n4; i += 256) dst[i] = __ldg(src + i);
        }
        __syncthreads();

        for (int g = gs; g < ge; ++g) {
            const int baseG = (g << 7) + (lane << 2);

            if (g + 1 < NG) {
                const float* nb = planeBase + (size_t)(((g + 1) << 7) + (lane << 2));
                asm volatile("prefetch.global.L2 [%0];" :: "l"(nb));
                asm volatile("prefetch.global.L2 [%0];" :: "l"(nb + HW));
                asm volatile("prefetch.global.L2 [%0];" :: "l"(nb + 2 * (size_t)HW));
                asm volatile("prefetch.global.L2 [%0];" :: "l"(nb + 3 * (size_t)HW));
            }

            float4 V0 = __ldg((const float4*)(planeBase + baseG));
            float4 V1 = __ldg((const float4*)(planeBase + HW + baseG));
            float4 V2 = __ldg((const float4*)(planeBase + 2 * (size_t)HW + baseG));
            float4 V3 = __ldg((const float4*)(planeBase + 3 * (size_t)HW + baseG));
            int4 L = *(const int4*)(slab + ((g - gs) << 7) + (lane << 2));

            const int   lv[4] = {L.x, L.y, L.z, L.w};
            const float c0[4] = {V0.x, V0.y, V0.z, V0.w};
            const float c1[4] = {V1.x, V1.y, V1.z, V1.w};
            const float c2[4] = {V2.x, V2.y, V2.z, V2.w};
            const float c3[4] = {V3.x, V3.y, V3.z, V3.w};

            #pragma unroll
            for (int j = 0; j < 4; ++j) {
                const int   label = lv[j];
                const float v0 = c0[j], v1 = c1[j], v2 = c2[j], v3 = c3[j];

                const unsigned grp  = __match_any_sync(FULLMASK, label);
                const int      rank = __popc(grp & ((1u << lane) - 1u));
                const int      mx   = __reduce_max_sync(FULLMASK, rank);

                // round 0 (always): rank-0 lanes have distinct labels
                if (rank == 0) {
                    float2 x = pairA[label]; x.x += v0; x.y += v1; pairA[label] = x;
                    float2 y = pairB[label]; y.x += v2; y.y += v3; pairB[label] = y;
                    if (doCnt) cnt[label] += (float)__popc(grp);
                }
                // rare extra rounds for duplicate lanes (mx>=1 ~62%, >=2 ~2%)
                for (int r = 1; r <= mx; ++r) {
                    if (rank == r) {
                        float2 x = pairA[label]; x.x += v0; x.y += v1; pairA[label] = x;
                        float2 y = pairB[label]; y.x += v2; y.y += v3; pairB[label] = y;
                    }
                }
            }
        }
    }
    __syncthreads();

    // ---- merge partials into global scratch ----
    for (int r = tid; r < NLAB; r += 256) {
        const int   L = r + 1;
        const float c = cnt[L];
        if (c != 0.f) {
            const int gi = b * NLAB + r;
            float* po = g_acc + (size_t)gi * C;
            float* to = g_acc + 32768 + (size_t)gi * C;
            #pragma unroll
            for (int k = 0; k < 16; k += 4)    // pred channels k..k+3
                red4(po + k,
                     sm[(k >> 1) * PROW + 2 * L],     sm[(k >> 1) * PROW + 2 * L + 1],
                     sm[(k >> 1 | 1) * PROW + 2 * L], sm[(k >> 1 | 1) * PROW + 2 * L + 1]);
            #pragma unroll
            for (int k = 0; k < 16; k += 4)    // targ channels
                red4(to + k,
                     sm[(8 + (k >> 1)) * PROW + 2 * L],     sm[(8 + (k >> 1)) * PROW + 2 * L + 1],
                     sm[(8 + (k >> 1 | 1)) * PROW + 2 * L], sm[(8 + (k >> 1 | 1)) * PROW + 2 * L + 1]);
            atomicAdd(g_acc + 65536 + gi, c);
        }
    }
    __threadfence();
    __syncthreads();
    if (tid == 0) lastFlag = (atomicAdd(&g_done, 1u) == (unsigned)(nCTA - 1));
    __syncthreads();

    // ---- last CTA: finalize into d_out, re-zero scratch ----
    if (lastFlag) {
        __threadfence();
        const float4 z = make_float4(0.f, 0.f, 0.f, 0.f);
        for (int i = tid; i < 4 * NLAB; i += 256) {
            const float c = g_acc[65536 + i];
            const float inv = 1.0f / fmaxf(c, 1.0f);
            float4* gp = reinterpret_cast<float4*>(g_acc + (size_t)i * C);
            float4* gt = reinterpret_cast<float4*>(g_acc + 32768 + (size_t)i * C);
            float4* op = reinterpret_cast<float4*>(out + (size_t)i * C);
            float4* ot = reinterpret_cast<float4*>(out + 32768 + (size_t)i * C);
            #pragma unroll
            for (int q = 0; q < 4; ++q) {
                float4 vp = gp[q], vt = gt[q];
                vp.x *= inv; vp.y *= inv; vp.z *= inv; vp.w *= inv;
                vt.x *= inv; vt.y *= inv; vt.z *= inv; vt.w *= inv;
                op[q] = vp; ot[q] = vt;
                gp[q] = z;  gt[q] = z;
            }
            out[65536 + i]   = (c > 0.f) ? (float)((i & (NLAB - 1)) + 1) : 0.f;
            g_acc[65536 + i] = 0.f;
        }
        __syncthreads();
        if (tid == 0) g_done = 0u;
    }
}

extern "C" void kernel_launch(void* const* d_in, const int* in_sizes, int n_in,
                              void* d_out, int out_size)
{
    const float* pred = (const float*)d_in[0];
    const float* targ = (const float*)d_in[1];
    const int*   nuc  = (const int*)d_in[2];
    float* out = (float*)d_out;

    const int B = in_sizes[2] / HW;   // 4

    const int smemB = SMEM_F * (int)sizeof(float);
    cudaFuncSetAttribute(fused_kernel,
                         cudaFuncAttributeMaxDynamicSharedMemorySize, smemB);

    dim3 grid(STRIPS, B);
    fused_kernel<<<grid, 256, smemB>>>(pred, targ, nuc, out, STRIPS * B);
}